// round 2
// baseline (speedup 1.0000x reference)
#include <cuda_runtime.h>
#include <cuda_bf16.h>
#include <math.h>

// Problem constants
#define B_   8
#define L_   1024
#define H_   8
#define D_   32
#define C_   256
#define QT   64      // query tile
#define KT   64      // key tile
#define NKT  (L_ / KT)
#define SCALE 0.17677669529663687f  // 1/sqrt(32)

// mask dtype mode: 0 = float32, 1 = int32, 2 = uint8
__device__ int g_mask_mode;

__global__ void detect_mask_mode(const unsigned int* m)
{
    // Inspect first 2048 words (8192 bytes; safe for all candidate layouts:
    // u8 buffer = 8192 B, i32/f32 buffers = 32768 B).
    bool all_f32 = true, all_i32 = true;
    for (int i = 0; i < 2048; ++i) {
        unsigned int w = m[i];
        if (w != 0u && w != 0x3f800000u) all_f32 = false;
        if (w != 0u && w != 1u)          all_i32 = false;
    }
    g_mask_mode = all_f32 ? 0 : (all_i32 ? 1 : 2);
}

__device__ __forceinline__ bool mask_at(const void* m, int idx, int mode)
{
    if (mode == 0) return ((const float*)m)[idx] != 0.0f;
    if (mode == 1) return ((const int*)m)[idx]   != 0;
    return ((const unsigned char*)m)[idx] != 0;
}

__global__ __launch_bounds__(256, 1)
void masked_attn_kernel(const float* __restrict__ q,
                        const float* __restrict__ k,
                        const float* __restrict__ v,
                        const void* __restrict__ mask,
                        const float* __restrict__ bias,
                        float* __restrict__ out)
{
    // block -> (b, h, q-tile)
    int blk = blockIdx.x;
    int qt  = blk & 15;          // 16 q-tiles
    int h   = (blk >> 4) & 7;
    int b   = blk >> 7;
    int q0  = qt * QT;

    __shared__ float Qs[QT * 33];     // [r][d], pad 33
    __shared__ float Ktr[D_ * 65];    // [d][j], pad 65 (transposed K)
    __shared__ float Vs[KT * 36];     // [j][c], pad 36 (float4-aligned)
    __shared__ float Ss[QT * 65];     // [r][j], pad 65
    __shared__ float Madd[KT];

    int mode = g_mask_mode;

    int t  = threadIdx.x;
    int tx = t & 15, ty = t >> 4;     // score-phase mapping (16x16 threads)
    int r  = t >> 2, sub = t & 3;     // row mapping (4 threads / query row)

    // ---- load Q tile (coalesced 128B per warp) ----
    const float* qbase = q + ((size_t)(b * L_ + q0)) * C_ + h * D_;
    for (int i = t; i < QT * D_; i += 256) {
        int rr = i >> 5, dd = i & 31;
        Qs[rr * 33 + dd] = qbase[(size_t)rr * C_ + dd];
    }

    float m = -INFINITY, l = 0.f;
    float acc[8];
    #pragma unroll
    for (int c = 0; c < 8; ++c) acc[c] = 0.f;

    for (int kt = 0; kt < NKT; ++kt) {
        int k0 = kt * KT;
        __syncthreads();   // previous iteration's reads of Vs/Ss done

        // ---- load K (transposed) and V tiles ----
        const float* kbase = k + ((size_t)(b * L_ + k0)) * C_ + h * D_;
        const float* vbase = v + ((size_t)(b * L_ + k0)) * C_ + h * D_;
        for (int i = t; i < KT * D_; i += 256) {
            int rr = i >> 5, dd = i & 31;
            float kv = kbase[(size_t)rr * C_ + dd];
            float vv = vbase[(size_t)rr * C_ + dd];
            Ktr[dd * 65 + rr] = kv;   // conflict-free: bank (dd+rr)%32
            Vs[rr * 36 + dd]  = vv;   // conflict-free: bank (4rr+dd)%32
        }
        if (t < KT)
            Madd[t] = mask_at(mask, b * L_ + k0 + t, mode) ? 0.f : -1e9f;
        __syncthreads();

        // ---- Phase A: scores 64x64, 4x4 register micro-tile ----
        // rows r = ty*4+ii, cols j = tx + 16*i  (bank-conflict-free column map)
        float a4[4][4];
        #pragma unroll
        for (int ii = 0; ii < 4; ++ii)
            #pragma unroll
            for (int i = 0; i < 4; ++i) a4[ii][i] = 0.f;

        #pragma unroll 8
        for (int d = 0; d < D_; ++d) {
            float kr[4], qr[4];
            #pragma unroll
            for (int i = 0; i < 4; ++i)  kr[i] = Ktr[d * 65 + tx + 16 * i];
            #pragma unroll
            for (int ii = 0; ii < 4; ++ii) qr[ii] = Qs[(ty * 4 + ii) * 33 + d];
            #pragma unroll
            for (int ii = 0; ii < 4; ++ii)
                #pragma unroll
                for (int i = 0; i < 4; ++i)
                    a4[ii][i] = fmaf(qr[ii], kr[i], a4[ii][i]);
        }

        #pragma unroll
        for (int ii = 0; ii < 4; ++ii) {
            int rr = ty * 4 + ii;
            const float* bp = bias + ((size_t)b * L_ + (q0 + rr)) * L_ + k0;
            #pragma unroll
            for (int i = 0; i < 4; ++i) {
                int jj = tx + 16 * i;
                Ss[rr * 65 + jj] = a4[ii][i] * SCALE + bp[jj] + Madd[jj];
            }
        }
        __syncthreads();

        // ---- Phase B: online softmax + P*V (4 threads per row) ----
        float* srow = &Ss[r * 65];
        float mt = -INFINITY;
        #pragma unroll
        for (int i = 0; i < 16; ++i) mt = fmaxf(mt, srow[sub * 16 + i]);
        mt = fmaxf(mt, __shfl_xor_sync(0xffffffffu, mt, 1));
        mt = fmaxf(mt, __shfl_xor_sync(0xffffffffu, mt, 2));

        float mnew   = fmaxf(m, mt);
        float factor = __expf(m - mnew);
        l *= factor;
        #pragma unroll
        for (int c = 0; c < 8; ++c) acc[c] *= factor;

        #pragma unroll
        for (int i = 0; i < 16; ++i) {
            float p = __expf(srow[sub * 16 + i] - mnew);
            l += p;
            srow[sub * 16 + i] = p;   // write p back (same warp reads below)
        }
        __syncwarp();

        #pragma unroll 4
        for (int j = 0; j < KT; ++j) {
            float p = srow[j];  // broadcast within 4-lane group
            const float4* vp = (const float4*)&Vs[j * 36 + sub * 8];
            float4 v0 = vp[0], v1 = vp[1];
            acc[0] = fmaf(p, v0.x, acc[0]);
            acc[1] = fmaf(p, v0.y, acc[1]);
            acc[2] = fmaf(p, v0.z, acc[2]);
            acc[3] = fmaf(p, v0.w, acc[3]);
            acc[4] = fmaf(p, v1.x, acc[4]);
            acc[5] = fmaf(p, v1.y, acc[5]);
            acc[6] = fmaf(p, v1.z, acc[6]);
            acc[7] = fmaf(p, v1.w, acc[7]);
        }
        m = mnew;
    }

    // ---- epilogue ----
    l += __shfl_xor_sync(0xffffffffu, l, 1);
    l += __shfl_xor_sync(0xffffffffu, l, 2);
    float inv = 1.f / l;

    int qrow = q0 + r;
    bool act = mask_at(mask, b * L_ + qrow, mode);
    float* op       = out + ((size_t)(b * L_ + qrow)) * C_ + h * D_ + sub * 8;
    const float* vp = v   + ((size_t)(b * L_ + qrow)) * C_ + h * D_ + sub * 8;

    float4 o0, o1;
    if (act) {
        o0 = make_float4(acc[0] * inv, acc[1] * inv, acc[2] * inv, acc[3] * inv);
        o1 = make_float4(acc[4] * inv, acc[5] * inv, acc[6] * inv, acc[7] * inv);
    } else {
        o0 = ((const float4*)vp)[0];
        o1 = ((const float4*)vp)[1];
    }
    ((float4*)op)[0] = o0;
    ((float4*)op)[1] = o1;
}

extern "C" void kernel_launch(void* const* d_in, const int* in_sizes, int n_in,
                              void* d_out, int out_size)
{
    // Resolve input ordering from element counts:
    //   bias = 8*1024*1024 = 8388608, mask = 8*1024 = 8192, q/k/v = 2097152.
    const int QKV_N  = B_ * L_ * C_;
    const int BIAS_N = B_ * L_ * L_;
    const int MASK_N = B_ * L_;

    int bias_i = -1, mask_i = -1;
    int big[3]; int nbig = 0;
    for (int i = 0; i < n_in; ++i) {
        if (in_sizes[i] == BIAS_N) bias_i = i;
        else if (in_sizes[i] == MASK_N) mask_i = i;
        else if (in_sizes[i] == QKV_N && nbig < 3) big[nbig++] = i;
    }

    const float* q; const float* k; const float* v;
    if (bias_i == 0) {
        // alphabetical metadata order: bias, hard_mask, key, query, value
        k = (const float*)d_in[big[0]];
        q = (const float*)d_in[big[1]];
        v = (const float*)d_in[big[2]];
    } else {
        // dict order: query, key, value, hard_mask, bias
        q = (const float*)d_in[big[0]];
        k = (const float*)d_in[big[1]];
        v = (const float*)d_in[big[2]];
    }
    const void*  mask = d_in[mask_i];
    const float* bias = (const float*)d_in[bias_i];
    float*       out  = (float*)d_out;

    detect_mask_mode<<<1, 1>>>((const unsigned int*)mask);

    dim3 grid(B_ * H_ * (L_ / QT));   // 1024 blocks
    dim3 block(256);
    masked_attn_kernel<<<grid, block>>>(q, k, v, mask, bias, out);
}

// round 4
// speedup vs baseline: 1.4088x; 1.4088x over previous
#include <cuda_runtime.h>
#include <cuda_bf16.h>
#include <math.h>

#define B_   8
#define L_   1024
#define H_   8
#define D_   32
#define C_   256
#define QT   128     // query tile
#define KT   64      // key tile
#define NKT  (L_ / KT)
#define SCALE 0.17677669529663687f  // 1/sqrt(32)

// smem layout (floats)
#define QTR_OFF  0                      // Qtr[32][128] swizzled, 4096
#define KTR_OFF  (QTR_OFF + 32*128)     // Ktr[32][64]  swizzled, 2048
#define VS_OFF   (KTR_OFF + 32*64)      // Vs[64][36], 2304
#define SS_OFF   (VS_OFF  + 64*36)      // Ss[128][68], 8704
#define MADD_OFF (SS_OFF  + 128*68)     // Madd[64]
#define SMEM_FLOATS (MADD_OFF + 64)
#define SMEM_BYTES  (SMEM_FLOATS * 4)   // 68864 B

// mask dtype mode: 0 = float32, 1 = int32, 2 = uint8
__device__ int g_mask_mode;

__global__ void detect_mask_mode(const unsigned int* m)
{
    bool all_f32 = true, all_i32 = true;
    for (int i = 0; i < 2048; ++i) {
        unsigned int w = m[i];
        if (w != 0u && w != 0x3f800000u) all_f32 = false;
        if (w != 0u && w != 1u)          all_i32 = false;
    }
    g_mask_mode = all_f32 ? 0 : (all_i32 ? 1 : 2);
}

__device__ __forceinline__ bool mask_at(const void* m, int idx, int mode)
{
    if (mode == 0) return ((const float*)m)[idx] != 0.0f;
    if (mode == 1) return ((const int*)m)[idx]   != 0;
    return ((const unsigned char*)m)[idx] != 0;
}

// ---- f32x2 packed helpers (sm_10x) ----
typedef unsigned long long ull;

__device__ __forceinline__ ull pack2(float x, float y) {
    ull r; asm("mov.b64 %0, {%1,%2};" : "=l"(r) : "f"(x), "f"(y)); return r;
}
__device__ __forceinline__ void unpack2(ull a, float& x, float& y) {
    asm("mov.b64 {%0,%1}, %2;" : "=f"(x), "=f"(y) : "l"(a));
}
__device__ __forceinline__ ull ffma2(ull a, ull b, ull c) {
    ull r; asm("fma.rn.f32x2 %0, %1, %2, %3;" : "=l"(r) : "l"(a), "l"(b), "l"(c)); return r;
}
__device__ __forceinline__ ull fmul2(ull a, ull b) {
    ull r; asm("mul.rn.f32x2 %0, %1, %2;" : "=l"(r) : "l"(a), "l"(b)); return r;
}

__global__ __launch_bounds__(256, 2)
void masked_attn_kernel(const float* __restrict__ q,
                        const float* __restrict__ k,
                        const float* __restrict__ v,
                        const void* __restrict__ mask,
                        const float* __restrict__ bias,
                        float* __restrict__ out)
{
    extern __shared__ float sm[];
    float* Qtr  = sm + QTR_OFF;
    float* Ktr  = sm + KTR_OFF;
    float* Vs   = sm + VS_OFF;
    float* Ss   = sm + SS_OFF;
    float* Madd = sm + MADD_OFF;

    // block -> (b, h, q-tile)
    int blk = blockIdx.x;
    int qt  = blk & 7;            // 8 q-tiles of 128
    int h   = (blk >> 3) & 7;
    int b   = blk >> 6;
    int q0  = qt * QT;

    int mode = g_mask_mode;
    int t  = threadIdx.x;
    int tx = t & 15, ty = t >> 4;  // Phase A: cols tx*4..+3, rows ty*8..+7
    int r  = t >> 1, sub = t & 1;  // Phase B: row r, c-range sub*16..+15

    // ---- load Q tile transposed+swizzled: Qtr[d][r] ----
    {
        const float* qbase = q + ((size_t)(b * L_ + q0)) * C_ + h * D_;
        #pragma unroll
        for (int it = 0; it < 16; ++it) {
            int i  = t + it * 256;
            int rr = i >> 5, dd = i & 31;
            float qv = qbase[(size_t)rr * C_ + dd];
            int addr = dd * 128 + ((((rr >> 2) ^ (dd & 15)) << 2) | (rr & 3));
            Qtr[addr] = qv;
        }
    }

    float m = -INFINITY, l = 0.f;
    ull acc[8];
    #pragma unroll
    for (int c = 0; c < 8; ++c) acc[c] = 0ull;

    for (int kt = 0; kt < NKT; ++kt) {
        int k0 = kt * KT;
        __syncthreads();   // prev iteration's reads of Ktr/Vs done

        // ---- load K (transposed+swizzled) and V tiles ----
        const float* kbase = k + ((size_t)(b * L_ + k0)) * C_ + h * D_;
        const float* vbase = v + ((size_t)(b * L_ + k0)) * C_ + h * D_;
        #pragma unroll
        for (int it = 0; it < 8; ++it) {
            int i  = t + it * 256;
            int rr = i >> 5, dd = i & 31;
            float kv = kbase[(size_t)rr * C_ + dd];
            float vv = vbase[(size_t)rr * C_ + dd];
            int kaddr = dd * 64 + ((((rr >> 2) ^ (dd & 15)) << 2) | (rr & 3));
            Ktr[kaddr]       = kv;
            Vs[rr * 36 + dd] = vv;
        }
        if (t < KT)
            Madd[t] = mask_at(mask, b * L_ + k0 + t, mode) ? 0.f : -1e9f;
        __syncthreads();

        // ---- Phase A: scores 128x64, 8x4 micro-tile, packed f32x2 ----
        ull a2[4][4];   // [row-pair][col]
        #pragma unroll
        for (int rp = 0; rp < 4; ++rp)
            #pragma unroll
            for (int i = 0; i < 4; ++i) a2[rp][i] = 0ull;

        #pragma unroll 8
        for (int d = 0; d < D_; ++d) {
            int sw = d & 15;
            float4 kf = *(const float4*)&Ktr[d * 64 + ((tx ^ sw) << 2)];
            ull kk[4];
            kk[0] = pack2(kf.x, kf.x);
            kk[1] = pack2(kf.y, kf.y);
            kk[2] = pack2(kf.z, kf.z);
            kk[3] = pack2(kf.w, kf.w);
            ulonglong2 qa = *(const ulonglong2*)&Qtr[d * 128 + (((2 * ty)     ^ sw) << 2)];
            ulonglong2 qb = *(const ulonglong2*)&Qtr[d * 128 + (((2 * ty + 1) ^ sw) << 2)];
            ull q2[4] = { qa.x, qa.y, qb.x, qb.y };  // row pairs (8ty+0,1)(2,3)(4,5)(6,7)
            #pragma unroll
            for (int rp = 0; rp < 4; ++rp)
                #pragma unroll
                for (int i = 0; i < 4; ++i)
                    a2[rp][i] = ffma2(q2[rp], kk[i], a2[rp][i]);
        }

        // scale + bias + mask, write Ss
        {
            float4 madd4 = *(const float4*)&Madd[tx * 4];
            #pragma unroll
            for (int rp = 0; rp < 4; ++rp) {
                float s0[4], s1[4];
                #pragma unroll
                for (int i = 0; i < 4; ++i) unpack2(a2[rp][i], s0[i], s1[i]);
                #pragma unroll
                for (int e = 0; e < 2; ++e) {
                    int rr = ty * 8 + rp * 2 + e;
                    const float* sp = e ? s1 : s0;
                    float4 bp = *(const float4*)&bias[((size_t)b * L_ + (q0 + rr)) * L_ + k0 + tx * 4];
                    float4 sv;
                    sv.x = fmaf(sp[0], SCALE, bp.x + madd4.x);
                    sv.y = fmaf(sp[1], SCALE, bp.y + madd4.y);
                    sv.z = fmaf(sp[2], SCALE, bp.z + madd4.z);
                    sv.w = fmaf(sp[3], SCALE, bp.w + madd4.w);
                    *(float4*)&Ss[rr * 68 + tx * 4] = sv;
                }
            }
        }
        __syncwarp();   // Ss rows [16w,16w+16) produced & consumed by warp w only

        // ---- Phase B: online softmax + P*V ----
        float* srow = &Ss[r * 68];
        int jb = sub * 32;
        float mt = -INFINITY;
        #pragma unroll
        for (int g = 0; g < 8; ++g) {
            float4 sv = *(const float4*)&srow[jb + 4 * g];
            mt = fmaxf(mt, fmaxf(fmaxf(sv.x, sv.y), fmaxf(sv.z, sv.w)));
        }
        mt = fmaxf(mt, __shfl_xor_sync(0xffffffffu, mt, 1));

        float mnew   = fmaxf(m, mt);
        float factor = __expf(m - mnew);
        l *= factor;
        ull f2 = pack2(factor, factor);
        #pragma unroll
        for (int c = 0; c < 8; ++c) acc[c] = fmul2(acc[c], f2);

        #pragma unroll
        for (int g = 0; g < 8; ++g) {
            float4 sv = *(const float4*)&srow[jb + 4 * g];
            sv.x = __expf(sv.x - mnew);
            sv.y = __expf(sv.y - mnew);
            sv.z = __expf(sv.z - mnew);
            sv.w = __expf(sv.w - mnew);
            l += sv.x + sv.y + sv.z + sv.w;
            *(float4*)&srow[jb + 4 * g] = sv;
        }
        __syncwarp();

        const float* vsb = &Vs[sub * 16];
        #pragma unroll 2
        for (int jq = 0; jq < 16; ++jq) {
            float4 pf = *(const float4*)&srow[jq * 4];
            ull pp[4];
            pp[0] = pack2(pf.x, pf.x);
            pp[1] = pack2(pf.y, pf.y);
            pp[2] = pack2(pf.z, pf.z);
            pp[3] = pack2(pf.w, pf.w);
            #pragma unroll
            for (int u = 0; u < 4; ++u) {
                const float* vrow = vsb + (jq * 4 + u) * 36;
                // 16 channels = 4x ulonglong2 (each 4 floats) at offsets 0,4,8,12
                ulonglong2 v01 = *(const ulonglong2*)&vrow[0];
                ulonglong2 v23 = *(const ulonglong2*)&vrow[4];
                acc[0] = ffma2(pp[u], v01.x, acc[0]);
                acc[1] = ffma2(pp[u], v01.y, acc[1]);
                acc[2] = ffma2(pp[u], v23.x, acc[2]);
                acc[3] = ffma2(pp[u], v23.y, acc[3]);
                ulonglong2 v45 = *(const ulonglong2*)&vrow[8];
                ulonglong2 v67 = *(const ulonglong2*)&vrow[12];
                acc[4] = ffma2(pp[u], v45.x, acc[4]);
                acc[5] = ffma2(pp[u], v45.y, acc[5]);
                acc[6] = ffma2(pp[u], v67.x, acc[6]);
                acc[7] = ffma2(pp[u], v67.y, acc[7]);
            }
        }
        m = mnew;
    }

    // ---- epilogue ----
    l += __shfl_xor_sync(0xffffffffu, l, 1);
    float inv = 1.f / l;

    int qrow = q0 + r;
    bool act = mask_at(mask, b * L_ + qrow, mode);
    float* op       = out + ((size_t)(b * L_ + qrow)) * C_ + h * D_ + sub * 16;
    const float* vp = v   + ((size_t)(b * L_ + qrow)) * C_ + h * D_ + sub * 16;

    if (act) {
        #pragma unroll
        for (int g = 0; g < 4; ++g) {
            float x0, x1, x2, x3;
            unpack2(acc[2 * g],     x0, x1);
            unpack2(acc[2 * g + 1], x2, x3);
            float4 o = make_float4(x0 * inv, x1 * inv, x2 * inv, x3 * inv);
            ((float4*)op)[g] = o;
        }
    } else {
        #pragma unroll
        for (int g = 0; g < 4; ++g)
            ((float4*)op)[g] = ((const float4*)vp)[g];
    }
}

extern "C" void kernel_launch(void* const* d_in, const int* in_sizes, int n_in,
                              void* d_out, int out_size)
{
    const int QKV_N  = B_ * L_ * C_;
    const int BIAS_N = B_ * L_ * L_;
    const int MASK_N = B_ * L_;

    int bias_i = -1, mask_i = -1;
    int big[3]; int nbig = 0;
    for (int i = 0; i < n_in; ++i) {
        if (in_sizes[i] == BIAS_N) bias_i = i;
        else if (in_sizes[i] == MASK_N) mask_i = i;
        else if (in_sizes[i] == QKV_N && nbig < 3) big[nbig++] = i;
    }

    const float* q; const float* k; const float* v;
    if (bias_i == 0) {  // alphabetical order: bias, hard_mask, key, query, value
        k = (const float*)d_in[big[0]];
        q = (const float*)d_in[big[1]];
        v = (const float*)d_in[big[2]];
    } else {            // dict order: query, key, value, hard_mask, bias
        q = (const float*)d_in[big[0]];
        k = (const float*)d_in[big[1]];
        v = (const float*)d_in[big[2]];
    }
    const void*  mask = d_in[mask_i];
    const float* bias = (const float*)d_in[bias_i];
    float*       out  = (float*)d_out;

    cudaFuncSetAttribute(masked_attn_kernel,
                         cudaFuncAttributeMaxDynamicSharedMemorySize, SMEM_BYTES);

    detect_mask_mode<<<1, 1>>>((const unsigned int*)mask);

    dim3 grid(B_ * H_ * (L_ / QT));   // 512 blocks
    dim3 block(256);
    masked_attn_kernel<<<grid, block, SMEM_BYTES>>>(q, k, v, mask, bias, out);
}